// round 1
// baseline (speedup 1.0000x reference)
#include <cuda_runtime.h>

static constexpr int VOCAB = 25000;
static constexpr int V4 = VOCAB / 4;   // 6250, row byte-stride 100000 is 16B aligned
static constexpr int THREADS = 256;

// log1p(f) for f in [-1/3, 1/3]:  f + f^2 * P(f), Taylor degree 7.
// Max abs error ~1.9e-5 (first omitted term (1/3)^8/8), far under tolerance.
__device__ __forceinline__ float log1p_poly(float f) {
    float p = 0.142857143f;               // 1/7
    p = fmaf(p, f, -0.166666667f);        // -1/6
    p = fmaf(p, f,  0.200000000f);        //  1/5
    p = fmaf(p, f, -0.250000000f);        // -1/4
    p = fmaf(p, f,  0.333333333f);        //  1/3
    p = fmaf(p, f, -0.500000000f);        // -1/2
    return fmaf(p, f * f, f);
}

// log(q) - log(p) without MUFU: integer exponent extraction centers the
// mantissa in [2/3, 4/3) (njuffa trick), exponents combine exactly in int.
__device__ __forceinline__ float log_ratio(float q, float p) {
    int iq = __float_as_int(q), ip = __float_as_int(p);
    int eq = (iq - 0x3f2aaaab) & 0xff800000;
    int ep = (ip - 0x3f2aaaab) & 0xff800000;
    float fq = __int_as_float(iq - eq) - 1.0f;
    float fp = __int_as_float(ip - ep) - 1.0f;
    float ed = (float)(eq - ep);          // exact: multiple of 2^23, fits int32
    // ln(2) / 2^23
    return fmaf(ed, 8.26295788e-8f, log1p_poly(fq) - log1p_poly(fp));
}

__global__ void __launch_bounds__(THREADS)
kl_kernel(const float* __restrict__ p, const float* __restrict__ q,
          float* __restrict__ out, float inv_rows) {
    const int row = blockIdx.x;
    const float4* p4 = reinterpret_cast<const float4*>(p + (size_t)row * VOCAB);
    const float4* q4 = reinterpret_cast<const float4*>(q + (size_t)row * VOCAB);

    float acc  = 0.0f;
    float vmax = -1.0f;   // inputs are strictly positive

    for (int idx = threadIdx.x; idx < V4; idx += THREADS) {
        float4 pv = __ldg(p4 + idx);
        float4 qv = __ldg(q4 + idx);
        acc = fmaf(qv.x, log_ratio(qv.x, pv.x), acc);
        acc = fmaf(qv.y, log_ratio(qv.y, pv.y), acc);
        acc = fmaf(qv.z, log_ratio(qv.z, pv.z), acc);
        acc = fmaf(qv.w, log_ratio(qv.w, pv.w), acc);
        vmax = fmaxf(vmax, fmaxf(fmaxf(pv.x, pv.y), fmaxf(pv.z, pv.w)));
    }

    // intra-warp reduction
    #pragma unroll
    for (int o = 16; o; o >>= 1) {
        acc  += __shfl_xor_sync(0xffffffffu, acc, o);
        vmax  = fmaxf(vmax, __shfl_xor_sync(0xffffffffu, vmax, o));
    }

    __shared__ float s_acc[THREADS / 32];
    __shared__ float s_max[THREADS / 32];
    const int wid = threadIdx.x >> 5;
    const int lid = threadIdx.x & 31;
    if (lid == 0) { s_acc[wid] = acc; s_max[wid] = vmax; }
    __syncthreads();

    if (threadIdx.x == 0) {
        float a = 0.0f, m = -1.0f;
        #pragma unroll
        for (int w = 0; w < THREADS / 32; w++) {
            a += s_acc[w];
            m  = fmaxf(m, s_max[w]);
        }
        // argmax(p_row) != 0  <=>  max(p_row) > p_row[0]
        // (argmax returns the FIRST max; a tie with index 0 means argmax==0)
        float p0 = __ldg(p + (size_t)row * VOCAB);
        if (m > p0) atomicAdd(out, a * inv_rows);
    }
}

__global__ void zero_kernel(float* out, int n) {
    int i = blockIdx.x * blockDim.x + threadIdx.x;
    if (i < n) out[i] = 0.0f;
}

extern "C" void kernel_launch(void* const* d_in, const int* in_sizes, int n_in,
                              void* d_out, int out_size) {
    const float* p = (const float*)d_in[0];
    const float* q = (const float*)d_in[1];
    float* out = (float*)d_out;

    const int total = in_sizes[0];      // D0*D1*V
    const int rows  = total / VOCAB;    // 4096

    zero_kernel<<<(out_size + 255) / 256, 256>>>(out, out_size);
    kl_kernel<<<rows, THREADS>>>(p, q, out, 1.0f / (float)rows);
}

// round 2
// speedup vs baseline: 1.0047x; 1.0047x over previous
#include <cuda_runtime.h>

static constexpr int VOCAB = 25000;
static constexpr int V4 = VOCAB / 4;     // 6250 float4 per row; row stride 100000 B is 16B aligned
static constexpr int THREADS = 256;
static constexpr int FULL_ITERS = V4 / (2 * THREADS);        // 12 (covers 6144)
static constexpr int TAIL_BASE = FULL_ITERS * 2 * THREADS;   // 6144
static constexpr int TAIL_CNT = V4 - TAIL_BASE;              // 106

// log1p(f) for f in [-1/3, 1/3]:  f + f^2 * P(f), Taylor degree 7.
// Max abs error ~1.9e-5, far under the 1e-3 tolerance (measured rel_err 7e-7).
__device__ __forceinline__ float log1p_poly(float f) {
    float p = 0.142857143f;               // 1/7
    p = fmaf(p, f, -0.166666667f);        // -1/6
    p = fmaf(p, f,  0.200000000f);        //  1/5
    p = fmaf(p, f, -0.250000000f);        // -1/4
    p = fmaf(p, f,  0.333333333f);        //  1/3
    p = fmaf(p, f, -0.500000000f);        // -1/2
    return fmaf(p, f * f, f);
}

// log(q) - log(p) without MUFU: integer exponent extraction centers the
// mantissa in [2/3, 4/3) (njuffa trick); exponents combine exactly in int.
__device__ __forceinline__ float log_ratio(float q, float p) {
    int iq = __float_as_int(q), ip = __float_as_int(p);
    int eq = (iq - 0x3f2aaaab) & 0xff800000;
    int ep = (ip - 0x3f2aaaab) & 0xff800000;
    float fq = __int_as_float(iq - eq) - 1.0f;
    float fp = __int_as_float(ip - ep) - 1.0f;
    float ed = (float)(eq - ep);          // exact: multiple of 2^23, fits int32
    return fmaf(ed, 8.26295788e-8f, log1p_poly(fq) - log1p_poly(fp));   // ln2/2^23
}

__device__ __forceinline__ void accum4(const float4& pv, const float4& qv,
                                       float& acc, float& vmax) {
    acc = fmaf(qv.x, log_ratio(qv.x, pv.x), acc);
    acc = fmaf(qv.y, log_ratio(qv.y, pv.y), acc);
    acc = fmaf(qv.z, log_ratio(qv.z, pv.z), acc);
    acc = fmaf(qv.w, log_ratio(qv.w, pv.w), acc);
    vmax = fmaxf(vmax, fmaxf(fmaxf(pv.x, pv.y), fmaxf(pv.z, pv.w)));
}

__global__ void __launch_bounds__(THREADS)
kl_kernel(const float* __restrict__ p, const float* __restrict__ q,
          float* __restrict__ out, float inv_rows) {
    const int row = blockIdx.x;
    const int tid = threadIdx.x;
    const float4* p4 = reinterpret_cast<const float4*>(p + (size_t)row * VOCAB);
    const float4* q4 = reinterpret_cast<const float4*>(q + (size_t)row * VOCAB);

    // hoist the mask operand load: it's an L2 hit later anyway, but free to start early
    const float p0 = __ldg(p + (size_t)row * VOCAB);

    float acc  = 0.0f;
    float vmax = -1.0f;   // inputs are strictly positive

    // Main loop: 4 independent LDG.128 issued back-to-back per iteration
    // (higher MLP_p1), streaming hint to evict-first in L1/L2.
    int idx = tid;
    #pragma unroll 2
    for (int k = 0; k < FULL_ITERS; k++, idx += 2 * THREADS) {
        float4 pv0 = __ldcs(p4 + idx);
        float4 qv0 = __ldcs(q4 + idx);
        float4 pv1 = __ldcs(p4 + idx + THREADS);
        float4 qv1 = __ldcs(q4 + idx + THREADS);
        accum4(pv0, qv0, acc, vmax);
        accum4(pv1, qv1, acc, vmax);
    }

    // Tail: elements [6144, 6250) — first 106 threads take one float4 each.
    if (tid < TAIL_CNT) {
        float4 pv = __ldcs(p4 + TAIL_BASE + tid);
        float4 qv = __ldcs(q4 + TAIL_BASE + tid);
        accum4(pv, qv, acc, vmax);
    }

    // intra-warp reduction
    #pragma unroll
    for (int o = 16; o; o >>= 1) {
        acc  += __shfl_xor_sync(0xffffffffu, acc, o);
        vmax  = fmaxf(vmax, __shfl_xor_sync(0xffffffffu, vmax, o));
    }

    __shared__ float s_acc[THREADS / 32];
    __shared__ float s_max[THREADS / 32];
    const int wid = tid >> 5;
    const int lid = tid & 31;
    if (lid == 0) { s_acc[wid] = acc; s_max[wid] = vmax; }
    __syncthreads();

    if (tid == 0) {
        float a = 0.0f, m = -1.0f;
        #pragma unroll
        for (int w = 0; w < THREADS / 32; w++) {
            a += s_acc[w];
            m  = fmaxf(m, s_max[w]);
        }
        // argmax(p_row) != 0  <=>  max(p_row) > p_row[0]
        // (argmax returns the FIRST max; a tie at index 0 means argmax==0)
        if (m > p0) atomicAdd(out, a * inv_rows);
    }
}

__global__ void zero_kernel(float* out, int n) {
    int i = blockIdx.x * blockDim.x + threadIdx.x;
    if (i < n) out[i] = 0.0f;
}

extern "C" void kernel_launch(void* const* d_in, const int* in_sizes, int n_in,
                              void* d_out, int out_size) {
    const float* p = (const float*)d_in[0];
    const float* q = (const float*)d_in[1];
    float* out = (float*)d_out;

    const int total = in_sizes[0];      // D0*D1*V = 102,400,000
    const int rows  = total / VOCAB;    // 4096

    zero_kernel<<<(out_size + 255) / 256, 256>>>(out, out_size);
    kl_kernel<<<rows, THREADS>>>(p, q, out, 1.0f / (float)rows);
}